// round 1
// baseline (speedup 1.0000x reference)
#include <cuda_runtime.h>
#include <math.h>

// Problem constants (fixed by the dataset)
constexpr int BATCH = 8;
constexpr int MTOK  = 1024;   // tokens m
constexpr int DIM   = 768;    // d
constexpr int NE    = 64;     // experts n
constexpr int PP    = 16;     // slots per expert p
constexpr int SLOTS = NE * PP;        // 1024
constexpr int HID   = 2 * DIM;        // 1536

// ---------------- scratch (static device memory; no allocations) ----------
__device__ float g_phin[SLOTS * DIM];           //  3 MB  [s][d]
__device__ float g_logits[BATCH * MTOK * SLOTS];// 33 MB  [b][m][s]
__device__ float g_Dmat[BATCH * MTOK * SLOTS];  // 33 MB  dispatch (softmax over m)
__device__ float g_Cmat[BATCH * MTOK * SLOTS];  // 33 MB  combine  (softmax over s)
__device__ float g_Xs[BATCH * SLOTS * DIM];     // 25 MB  [b][s][d]
__device__ float g_Xn[NE * BATCH * PP * DIM];   // 25 MB  [n][b*16+p][d]  (LN'ed, expert-major)
__device__ float g_Hb[NE * BATCH * PP * HID];   // 50 MB  [n][r][h]
__device__ float g_Ys[BATCH * SLOTS * DIM];     // 25 MB  [b][s][d]

// ---------------- small helpers -------------------------------------------
__device__ __forceinline__ float block_sum256(float v, float* sm) {
    int t = threadIdx.x;
    #pragma unroll
    for (int o = 16; o > 0; o >>= 1) v += __shfl_xor_sync(0xffffffffu, v, o);
    if ((t & 31) == 0) sm[t >> 5] = v;
    __syncthreads();
    if (t < 8) {
        float w = sm[t];
        #pragma unroll
        for (int o = 4; o > 0; o >>= 1) w += __shfl_xor_sync(0xffu, w, o);
        if (t == 0) sm[0] = w;
    }
    __syncthreads();
    v = sm[0];
    __syncthreads();
    return v;
}

__device__ __forceinline__ float block_max256(float v, float* sm) {
    int t = threadIdx.x;
    #pragma unroll
    for (int o = 16; o > 0; o >>= 1) v = fmaxf(v, __shfl_xor_sync(0xffffffffu, v, o));
    if ((t & 31) == 0) sm[t >> 5] = v;
    __syncthreads();
    if (t < 8) {
        float w = sm[t];
        #pragma unroll
        for (int o = 4; o > 0; o >>= 1) w = fmaxf(w, __shfl_xor_sync(0xffu, w, o));
        if (t == 0) sm[0] = w;
    }
    __syncthreads();
    v = sm[0];
    __syncthreads();
    return v;
}

// ---------------- phi normalization (over expert axis n) ------------------
__global__ void phi_norm_kernel(const float* __restrict__ phi) {
    int t = blockIdx.x * blockDim.x + threadIdx.x;  // over p*d = 12288
    if (t >= PP * DIM) return;
    float ss = 0.f;
    #pragma unroll 4
    for (int n = 0; n < NE; n++) {
        float v = phi[n * PP * DIM + t];
        ss += v * v;
    }
    float inv = rsqrtf(ss + 1e-6f);
    #pragma unroll 4
    for (int n = 0; n < NE; n++)
        g_phin[n * PP * DIM + t] = phi[n * PP * DIM + t] * inv;
}

// ---------------- generic tiled fp32 GEMM ---------------------------------
// MODE: 0 = NN (A: MxK, B: KxN), 1 = NT (A: MxK, B: NxK), 2 = TN (A: KxM, B: KxN)
// EPI:  0 = store, 1 = +bias, 2 = +bias then exact GELU, 3 = +bias then scatter
//       (scatter: blockIdx.z = expert, row r -> out[(r/16)*SLOTS + z*16 + (r%16)])
template<int MODE, int EPI>
__global__ __launch_bounds__(256)
void gemm_kernel(const float* __restrict__ A, const float* __restrict__ Bm,
                 float* __restrict__ Cm, const float* __restrict__ bias,
                 int Mq, int Nq, int Kq,
                 long long sA, long long sB, long long sC, long long sBias)
{
    __shared__ float As[16][64];
    __shared__ float Bs[16][64];

    const float* Ab = A + (long long)blockIdx.z * sA;
    const float* Bb = Bm + (long long)blockIdx.z * sB;
    const int i0 = blockIdx.x * 64;
    const int j0 = blockIdx.y * 64;
    const int t  = threadIdx.x;
    const int tx = t & 15, ty = t >> 4;

    float acc[4][4] = {};

    for (int k0 = 0; k0 < Kq; k0 += 16) {
        // ---- load A tile into As[k][i]
        if (MODE == 2) {  // TN: A is KxM, contiguous in i
            int e = t * 4;
            int k = e >> 6, i = e & 63;
            float4 v = *(const float4*)&Ab[(long long)(k0 + k) * Mq + i0 + i];
            *(float4*)&As[k][i] = v;
        } else {          // NN/NT: A is MxK, contiguous in k
            int e = t * 4;
            int i = e >> 4, k = e & 15;
            float4 v = *(const float4*)&Ab[(long long)(i0 + i) * Kq + k0 + k];
            As[k + 0][i] = v.x; As[k + 1][i] = v.y; As[k + 2][i] = v.z; As[k + 3][i] = v.w;
        }
        // ---- load B tile into Bs[k][j]
        if (MODE == 1) {  // NT: B is NxK, contiguous in k
            int e = t * 4;
            int j = e >> 4, k = e & 15;
            float4 v = *(const float4*)&Bb[(long long)(j0 + j) * Kq + k0 + k];
            Bs[k + 0][j] = v.x; Bs[k + 1][j] = v.y; Bs[k + 2][j] = v.z; Bs[k + 3][j] = v.w;
        } else {          // NN/TN: B is KxN, contiguous in j
            int e = t * 4;
            int k = e >> 6, j = e & 63;
            float4 v = *(const float4*)&Bb[(long long)(k0 + k) * Nq + j0 + j];
            *(float4*)&Bs[k][j] = v;
        }
        __syncthreads();

        #pragma unroll
        for (int k = 0; k < 16; k++) {
            float4 a4 = *(float4*)&As[k][ty * 4];
            float4 b4 = *(float4*)&Bs[k][tx * 4];
            float av[4] = {a4.x, a4.y, a4.z, a4.w};
            float bv[4] = {b4.x, b4.y, b4.z, b4.w};
            #pragma unroll
            for (int ii = 0; ii < 4; ii++)
                #pragma unroll
                for (int jj = 0; jj < 4; jj++)
                    acc[ii][jj] = fmaf(av[ii], bv[jj], acc[ii][jj]);
        }
        __syncthreads();
    }

    // ---- epilogue
    #pragma unroll
    for (int ii = 0; ii < 4; ii++) {
        int r = i0 + ty * 4 + ii;
        float* crow;
        if (EPI == 3) {
            long long rr = (long long)(r >> 4) * SLOTS + (long long)blockIdx.z * PP + (r & 15);
            crow = Cm + rr * Nq;
        } else {
            crow = Cm + (long long)blockIdx.z * sC + (long long)r * Nq;
        }
        #pragma unroll
        for (int jj = 0; jj < 4; jj++) {
            int c = j0 + tx * 4 + jj;
            float v = acc[ii][jj];
            if (EPI >= 1) v += bias[(long long)blockIdx.z * sBias + c];
            if (EPI == 2) v = 0.5f * v * (1.0f + erff(v * 0.70710678118654752f));
            crow[c] = v;
        }
    }
}

// ---------------- softmax over tokens m (columns) -> dispatch D -----------
__global__ void softmax_col_kernel(const float* __restrict__ L, float* __restrict__ Dout) {
    // grid (SLOTS/32, BATCH); block 256 = 32 cols x 8 row-groups
    const int tx = threadIdx.x & 31, ty = threadIdx.x >> 5;
    const int s = blockIdx.x * 32 + tx;
    const float* Lb = L + (long long)blockIdx.y * MTOK * SLOTS;
    float* Db = Dout + (long long)blockIdx.y * MTOK * SLOTS;
    __shared__ float red[8][32];

    float mx = -1e30f;
    for (int m = ty; m < MTOK; m += 8)
        mx = fmaxf(mx, Lb[(long long)m * SLOTS + s]);
    red[ty][tx] = mx;
    __syncthreads();
    if (ty == 0) {
        float v = red[0][tx];
        #pragma unroll
        for (int q = 1; q < 8; q++) v = fmaxf(v, red[q][tx]);
        red[0][tx] = v;
    }
    __syncthreads();
    mx = red[0][tx];
    __syncthreads();

    float sum = 0.f;
    for (int m = ty; m < MTOK; m += 8) {
        float e = __expf(Lb[(long long)m * SLOTS + s] - mx);
        Db[(long long)m * SLOTS + s] = e;
        sum += e;
    }
    red[ty][tx] = sum;
    __syncthreads();
    if (ty == 0) {
        float v = 0.f;
        #pragma unroll
        for (int q = 0; q < 8; q++) v += red[q][tx];
        red[0][tx] = v;
    }
    __syncthreads();
    float inv = 1.0f / red[0][tx];
    for (int m = ty; m < MTOK; m += 8)
        Db[(long long)m * SLOTS + s] *= inv;
}

// ---------------- softmax over slots s (rows) -> combine C ---------------
__global__ void softmax_row_kernel(const float* __restrict__ L, float* __restrict__ Cout) {
    // one block (256 threads) per (b, m) row
    const long long row = blockIdx.x;
    const float* Lr = L + row * SLOTS;
    float* Cr = Cout + row * SLOTS;
    __shared__ float sm[32];
    const int t = threadIdx.x;

    float v[4];
    float mx = -1e30f;
    #pragma unroll
    for (int q = 0; q < 4; q++) { v[q] = Lr[t + q * 256]; mx = fmaxf(mx, v[q]); }
    mx = block_max256(mx, sm);
    float sum = 0.f;
    #pragma unroll
    for (int q = 0; q < 4; q++) { v[q] = __expf(v[q] - mx); sum += v[q]; }
    sum = block_sum256(sum, sm);
    float inv = 1.0f / sum;
    #pragma unroll
    for (int q = 0; q < 4; q++) Cr[t + q * 256] = v[q] * inv;
}

// ---------------- LayerNorm + scatter to expert-major layout --------------
__global__ void ln_kernel(const float* __restrict__ Xs,
                          const float* __restrict__ g, const float* __restrict__ bta) {
    // one block per (b, s) row
    const long long row = blockIdx.x;
    const int b = (int)(row / SLOTS);
    const int s = (int)(row % SLOTS);
    const int n = s >> 4, p = s & 15;
    const float* xr = Xs + row * DIM;
    float* outr = g_Xn + ((long long)n * (BATCH * PP) + b * PP + p) * DIM;
    __shared__ float sm[32];
    const int t = threadIdx.x;

    float v[3];
    float ss = 0.f;
    #pragma unroll
    for (int q = 0; q < 3; q++) { v[q] = xr[t + q * 256]; ss += v[q]; }
    float mu = block_sum256(ss, sm) * (1.0f / DIM);
    float sv = 0.f;
    #pragma unroll
    for (int q = 0; q < 3; q++) { float d = v[q] - mu; sv += d * d; }
    float var = block_sum256(sv, sm) * (1.0f / DIM);
    float inv = rsqrtf(var + 1e-5f);
    #pragma unroll
    for (int q = 0; q < 3; q++) {
        int c = t + q * 256;
        outr[c] = (v[q] - mu) * inv * g[n * DIM + c] + bta[n * DIM + c];
    }
}

// ---------------- launch ---------------------------------------------------
extern "C" void kernel_launch(void* const* d_in, const int* in_sizes, int n_in,
                              void* d_out, int out_size) {
    const float* x    = (const float*)d_in[0];
    const float* phi  = (const float*)d_in[1];
    const float* ln_g = (const float*)d_in[2];
    const float* ln_b = (const float*)d_in[3];
    const float* w1   = (const float*)d_in[4];
    const float* b1   = (const float*)d_in[5];
    const float* w2   = (const float*)d_in[6];
    const float* b2   = (const float*)d_in[7];
    float* out = (float*)d_out;

    float *phin, *logits, *Dm, *Cmx, *Xs, *Xn, *Hb, *Ys;
    cudaGetSymbolAddress((void**)&phin,   g_phin);
    cudaGetSymbolAddress((void**)&logits, g_logits);
    cudaGetSymbolAddress((void**)&Dm,     g_Dmat);
    cudaGetSymbolAddress((void**)&Cmx,    g_Cmat);
    cudaGetSymbolAddress((void**)&Xs,     g_Xs);
    cudaGetSymbolAddress((void**)&Xn,     g_Xn);
    cudaGetSymbolAddress((void**)&Hb,     g_Hb);
    cudaGetSymbolAddress((void**)&Ys,     g_Ys);

    // 1) normalize phi over expert axis -> [s][d]
    phi_norm_kernel<<<(PP * DIM + 255) / 256, 256>>>(phi);

    // 2) logits[b] = X[b] (1024x768) * phin^T (768x1024)   [NT]
    gemm_kernel<1, 0><<<dim3(MTOK / 64, SLOTS / 64, BATCH), 256>>>(
        x, phin, logits, nullptr,
        MTOK, SLOTS, DIM,
        (long long)MTOK * DIM, 0LL, (long long)MTOK * SLOTS, 0LL);

    // 3) dispatch D: softmax over m (columns); combine C: softmax over s (rows)
    softmax_col_kernel<<<dim3(SLOTS / 32, BATCH), 256>>>(logits, Dm);
    softmax_row_kernel<<<BATCH * MTOK, 256>>>(logits, Cmx);

    // 4) Xs[b] = D[b]^T (1024x1024) * X[b] (1024x768)   [TN]
    gemm_kernel<2, 0><<<dim3(SLOTS / 64, DIM / 64, BATCH), 256>>>(
        Dm, x, Xs, nullptr,
        SLOTS, DIM, MTOK,
        (long long)MTOK * SLOTS, (long long)MTOK * DIM, (long long)SLOTS * DIM, 0LL);

    // 5) LayerNorm rows of Xs, scatter to expert-major [n][b*16+p][d]
    ln_kernel<<<BATCH * SLOTS, 256>>>(Xs, ln_g, ln_b);

    // 6) per-expert: H = GELU(Xn * W1 + b1)   [NN], z = expert
    gemm_kernel<0, 2><<<dim3((BATCH * PP) / 64, HID / 64, NE), 256>>>(
        Xn, w1, Hb, b1,
        BATCH * PP, HID, DIM,
        (long long)BATCH * PP * DIM, (long long)DIM * HID,
        (long long)BATCH * PP * HID, (long long)HID);

    // 7) per-expert: Ys = H * W2 + b2, scattered back to [b][s][d]   [NN]
    gemm_kernel<0, 3><<<dim3((BATCH * PP) / 64, DIM / 64, NE), 256>>>(
        Hb, w2, Ys, b2,
        BATCH * PP, DIM, HID,
        (long long)BATCH * PP * HID, (long long)HID * DIM,
        0LL, (long long)DIM);

    // 8) Y[b] = C[b] (1024x1024) * Ys[b] (1024x768)   [NN]
    gemm_kernel<0, 0><<<dim3(MTOK / 64, DIM / 64, BATCH), 256>>>(
        Cmx, Ys, out, nullptr,
        MTOK, DIM, SLOTS,
        (long long)MTOK * SLOTS, (long long)SLOTS * DIM, (long long)MTOK * DIM, 0LL);
}

// round 5
// speedup vs baseline: 1.3707x; 1.3707x over previous
#include <cuda_runtime.h>
#include <cuda_bf16.h>
#include <math.h>
#include <stdint.h>

// Problem constants (fixed by the dataset)
constexpr int BATCH = 8;
constexpr int MTOK  = 1024;   // tokens m
constexpr int DIM   = 768;    // d
constexpr int NE    = 64;     // experts n
constexpr int PP    = 16;     // slots per expert p
constexpr int SLOTS = NE * PP;        // 1024
constexpr int HID   = 2 * DIM;        // 1536

// ---------------- scratch (static device memory; no allocations) ----------
__device__ float g_phin[SLOTS * DIM];           //  [s][d]
__device__ float g_logits[BATCH * MTOK * SLOTS];//  [b][m][s]
__device__ float g_Dmat[BATCH * MTOK * SLOTS];  //  dispatch (softmax over m)
__device__ float g_Cmat[BATCH * MTOK * SLOTS];  //  combine  (softmax over s)
__device__ float g_Xs[BATCH * SLOTS * DIM];     //  [b][s][d]
__device__ float g_Xn[NE * BATCH * PP * DIM];   //  [n][b*16+p][d]
__device__ float g_Hb[NE * BATCH * PP * HID];   //  [n][r][h]
__device__ float g_Ys[BATCH * SLOTS * DIM];     //  [b][s][d]

// ==================== low-level helpers ====================
__device__ __forceinline__ uint32_t smem_u32(const void* p) {
    uint32_t a;
    asm("{ .reg .u64 t; cvta.to.shared.u64 t, %1; cvt.u32.u64 %0, t; }" : "=r"(a) : "l"(p));
    return a;
}
__device__ __forceinline__ void ldsm_x4(uint32_t* f, uint32_t addr) {
    asm volatile("ldmatrix.sync.aligned.m8n8.x4.shared.b16 {%0,%1,%2,%3}, [%4];"
        : "=r"(f[0]), "=r"(f[1]), "=r"(f[2]), "=r"(f[3]) : "r"(addr));
}
__device__ __forceinline__ void mma16816(float* c, const uint32_t* a, const uint32_t* b) {
    asm volatile("mma.sync.aligned.m16n8k16.row.col.f32.bf16.bf16.f32 "
        "{%0,%1,%2,%3}, {%4,%5,%6,%7}, {%8,%9}, {%0,%1,%2,%3};"
        : "+f"(c[0]), "+f"(c[1]), "+f"(c[2]), "+f"(c[3])
        : "r"(a[0]), "r"(a[1]), "r"(a[2]), "r"(a[3]), "r"(b[0]), "r"(b[1]));
}

// Swizzled offset into a [rows][32] bf16 tile with 64-byte rows.
// 16B chunk index XORed with ((row>>1)&3) -> conflict-free ldmatrix phases.
__device__ __forceinline__ int swz(int r, int byteCol) {
    return r * 64 + ((((byteCol >> 4) ^ ((r >> 1) & 3)) << 4)) + (byteCol & 15);
}

// ==================== tensor-core GEMM (mma.sync bf16x3) ====================
// C[M,N] = A x B, fp32 in/out, hi/lo bf16 split, 3 MMA passes (hh, h*lo, lo*h).
// MODE: 0 = NN (A: MxK, B: KxN), 1 = NT (A: MxK, B: NxK), 2 = TN (A: KxM, B: KxN)
// EPI:  0 = store, 2 = +bias then exact GELU, 3 = +bias then expert scatter
// Block tile 128x64, K-chunk 32. 8 warps, warp tile 32x32 (warp grid 4x2).
template<int MODE, int EPI>
__global__ __launch_bounds__(256, 2)
void tc_gemm(const float* __restrict__ A, const float* __restrict__ Bm,
             float* __restrict__ Cm, const float* __restrict__ bias,
             int Mq, int Nq, int Kq,
             long long sA, long long sB, long long sC, long long sBias)
{
    __shared__ __align__(128) char sAhi[128 * 64];
    __shared__ __align__(128) char sAlo[128 * 64];
    __shared__ __align__(128) char sBhi[64 * 64];
    __shared__ __align__(128) char sBlo[64 * 64];

    const int t = threadIdx.x;
    const int wid = t >> 5;
    const int lane = t & 31;
    const int warp_m = wid >> 1;       // 0..3
    const int warp_n = wid & 1;        // 0..1
    const int i0 = blockIdx.x * 128;
    const int j0 = blockIdx.y * 64;
    const float* Ab = A + (long long)blockIdx.z * sA;
    const float* Bb = Bm + (long long)blockIdx.z * sB;

    const uint32_t bAhi = smem_u32(sAhi), bAlo = smem_u32(sAlo);
    const uint32_t bBhi = smem_u32(sBhi), bBlo = smem_u32(sBlo);

    float acc[2][4][4];
    #pragma unroll
    for (int a = 0; a < 2; a++)
        #pragma unroll
        for (int b = 0; b < 4; b++)
            #pragma unroll
            for (int c = 0; c < 4; c++) acc[a][b][c] = 0.f;

    // precomputed ldmatrix offsets (depend only on lane)
    int aoff[2][2], boff[2][2];   // [subm/pair][ks]
    #pragma unroll
    for (int sm = 0; sm < 2; sm++)
        #pragma unroll
        for (int ks = 0; ks < 2; ks++)
            aoff[sm][ks] = swz(warp_m * 32 + sm * 16 + (lane & 15),
                               ks * 32 + ((lane >> 4) << 4));
    #pragma unroll
    for (int pr = 0; pr < 2; pr++)
        #pragma unroll
        for (int ks = 0; ks < 2; ks++)
            boff[pr][ks] = swz(warp_n * 32 + pr * 16 + ((lane >> 4) << 3) + (lane & 7),
                               ks * 32 + (((lane >> 3) & 1) << 4));

    for (int k0 = 0; k0 < Kq; k0 += 32) {
        // ---------- cooperative load + split + swizzled store ----------
        if (MODE == 2) {
            // A is KxM: 32 k-rows x 128 m, contiguous in m
            #pragma unroll
            for (int p = 0; p < 4; p++) {
                int k = p * 8 + (t >> 5);
                int m4 = (t & 31) * 4;
                float4 v = *(const float4*)&Ab[(long long)(k0 + k) * Mq + i0 + m4];
                float vv[4] = {v.x, v.y, v.z, v.w};
                #pragma unroll
                for (int i = 0; i < 4; i++) {
                    __nv_bfloat16 h = __float2bfloat16_rn(vv[i]);
                    __nv_bfloat16 l = __float2bfloat16_rn(vv[i] - __bfloat162float(h));
                    int off = swz(m4 + i, k * 2);
                    *(__nv_bfloat16*)(sAhi + off) = h;
                    *(__nv_bfloat16*)(sAlo + off) = l;
                }
            }
        } else {
            // A is MxK: 128 rows x 32 k, contiguous in k
            #pragma unroll
            for (int p = 0; p < 4; p++) {
                int row = p * 32 + (t >> 3);
                int k4 = (t & 7) * 4;
                float4 v = *(const float4*)&Ab[(long long)(i0 + row) * Kq + k0 + k4];
                __nv_bfloat162 h0 = __floats2bfloat162_rn(v.x, v.y);
                __nv_bfloat162 h1 = __floats2bfloat162_rn(v.z, v.w);
                float2 f0 = __bfloat1622float2(h0), f1 = __bfloat1622float2(h1);
                __nv_bfloat162 l0 = __floats2bfloat162_rn(v.x - f0.x, v.y - f0.y);
                __nv_bfloat162 l1 = __floats2bfloat162_rn(v.z - f1.x, v.w - f1.y);
                int off = swz(row, k4 * 2);
                uint2 hv, lv;
                hv.x = *(uint32_t*)&h0; hv.y = *(uint32_t*)&h1;
                lv.x = *(uint32_t*)&l0; lv.y = *(uint32_t*)&l1;
                *(uint2*)(sAhi + off) = hv;
                *(uint2*)(sAlo + off) = lv;
            }
        }
        if (MODE == 1) {
            // B is NxK: 64 rows x 32 k, contiguous in k
            #pragma unroll
            for (int p = 0; p < 2; p++) {
                int row = p * 32 + (t >> 3);
                int k4 = (t & 7) * 4;
                float4 v = *(const float4*)&Bb[(long long)(j0 + row) * Kq + k0 + k4];
                __nv_bfloat162 h0 = __floats2bfloat162_rn(v.x, v.y);
                __nv_bfloat162 h1 = __floats2bfloat162_rn(v.z, v.w);
                float2 f0 = __bfloat1622float2(h0), f1 = __bfloat1622float2(h1);
                __nv_bfloat162 l0 = __floats2bfloat162_rn(v.x - f0.x, v.y - f0.y);
                __nv_bfloat162 l1 = __floats2bfloat162_rn(v.z - f1.x, v.w - f1.y);
                int off = swz(row, k4 * 2);
                uint2 hv, lv;
                hv.x = *(uint32_t*)&h0; hv.y = *(uint32_t*)&h1;
                lv.x = *(uint32_t*)&l0; lv.y = *(uint32_t*)&l1;
                *(uint2*)(sBhi + off) = hv;
                *(uint2*)(sBlo + off) = lv;
            }
        } else {
            // B is KxN: 32 k-rows x 64 n, contiguous in n
            #pragma unroll
            for (int p = 0; p < 2; p++) {
                int k = p * 16 + (t >> 4);
                int n4 = (t & 15) * 4;
                float4 v = *(const float4*)&Bb[(long long)(k0 + k) * Nq + j0 + n4];
                float vv[4] = {v.x, v.y, v.z, v.w};
                #pragma unroll
                for (int i = 0; i < 4; i++) {
                    __nv_bfloat16 h = __float2bfloat16_rn(vv[i]);
                    __nv_bfloat16 l = __float2bfloat16_rn(vv[i] - __bfloat162float(h));
                    int off = swz(n4 + i, k * 2);
                    *(__nv_bfloat16*)(sBhi + off) = h;
                    *(__nv_bfloat16*)(sBlo + off) = l;
                }
            }
        }
        __syncthreads();

        // ---------- MMA: 2 k16 steps, 3 passes ----------
        #pragma unroll
        for (int ks = 0; ks < 2; ks++) {
            uint32_t a_hi[2][4], a_lo[2][4], b_hi[4][2], b_lo[4][2];
            #pragma unroll
            for (int sm = 0; sm < 2; sm++) {
                ldsm_x4(a_hi[sm], bAhi + aoff[sm][ks]);
                ldsm_x4(a_lo[sm], bAlo + aoff[sm][ks]);
            }
            #pragma unroll
            for (int pr = 0; pr < 2; pr++) {
                ldsm_x4(&b_hi[pr * 2][0], bBhi + boff[pr][ks]);
                ldsm_x4(&b_lo[pr * 2][0], bBlo + boff[pr][ks]);
            }
            #pragma unroll
            for (int sm = 0; sm < 2; sm++)
                #pragma unroll
                for (int sn = 0; sn < 4; sn++) {
                    mma16816(acc[sm][sn], a_hi[sm], b_hi[sn]);
                    mma16816(acc[sm][sn], a_hi[sm], b_lo[sn]);
                    mma16816(acc[sm][sn], a_lo[sm], b_hi[sn]);
                }
        }
        __syncthreads();
    }

    // ---------- epilogue ----------
    #pragma unroll
    for (int sm = 0; sm < 2; sm++) {
        #pragma unroll
        for (int half = 0; half < 2; half++) {
            int r = i0 + warp_m * 32 + sm * 16 + (lane >> 2) + half * 8;
            float* crow;
            if (EPI == 3) {
                long long rr = (long long)(r >> 4) * SLOTS + (long long)blockIdx.z * PP + (r & 15);
                crow = Cm + rr * Nq;
            } else {
                crow = Cm + (long long)blockIdx.z * sC + (long long)r * Nq;
            }
            #pragma unroll
            for (int sn = 0; sn < 4; sn++) {
                int c = j0 + warp_n * 32 + sn * 8 + (lane & 3) * 2;
                float v0 = acc[sm][sn][half * 2 + 0];
                float v1 = acc[sm][sn][half * 2 + 1];
                if (EPI >= 2) {
                    v0 += bias[(long long)blockIdx.z * sBias + c];
                    v1 += bias[(long long)blockIdx.z * sBias + c + 1];
                }
                if (EPI == 2) {
                    v0 = 0.5f * v0 * (1.0f + erff(v0 * 0.70710678118654752f));
                    v1 = 0.5f * v1 * (1.0f + erff(v1 * 0.70710678118654752f));
                }
                float2 st; st.x = v0; st.y = v1;
                *(float2*)&crow[c] = st;
            }
        }
    }
}

// ==================== small elementwise / reduction kernels ====================
__device__ __forceinline__ float block_sum256(float v, float* sm) {
    int t = threadIdx.x;
    #pragma unroll
    for (int o = 16; o > 0; o >>= 1) v += __shfl_xor_sync(0xffffffffu, v, o);
    if ((t & 31) == 0) sm[t >> 5] = v;
    __syncthreads();
    if (t < 8) {
        float w = sm[t];
        #pragma unroll
        for (int o = 4; o > 0; o >>= 1) w += __shfl_xor_sync(0xffu, w, o);
        if (t == 0) sm[0] = w;
    }
    __syncthreads();
    v = sm[0];
    __syncthreads();
    return v;
}
__device__ __forceinline__ float block_max256(float v, float* sm) {
    int t = threadIdx.x;
    #pragma unroll
    for (int o = 16; o > 0; o >>= 1) v = fmaxf(v, __shfl_xor_sync(0xffffffffu, v, o));
    if ((t & 31) == 0) sm[t >> 5] = v;
    __syncthreads();
    if (t < 8) {
        float w = sm[t];
        #pragma unroll
        for (int o = 4; o > 0; o >>= 1) w = fmaxf(w, __shfl_xor_sync(0xffu, w, o));
        if (t == 0) sm[0] = w;
    }
    __syncthreads();
    v = sm[0];
    __syncthreads();
    return v;
}

__global__ void phi_norm_kernel(const float* __restrict__ phi) {
    int t = blockIdx.x * blockDim.x + threadIdx.x;
    if (t >= PP * DIM) return;
    float ss = 0.f;
    #pragma unroll 4
    for (int n = 0; n < NE; n++) {
        float v = phi[n * PP * DIM + t];
        ss += v * v;
    }
    float inv = rsqrtf(ss + 1e-6f);
    #pragma unroll 4
    for (int n = 0; n < NE; n++)
        g_phin[n * PP * DIM + t] = phi[n * PP * DIM + t] * inv;
}

__global__ void softmax_col_kernel(const float* __restrict__ L, float* __restrict__ Dout) {
    const int tx = threadIdx.x & 31, ty = threadIdx.x >> 5;
    const int s = blockIdx.x * 32 + tx;
    const float* Lb = L + (long long)blockIdx.y * MTOK * SLOTS;
    float* Db = Dout + (long long)blockIdx.y * MTOK * SLOTS;
    __shared__ float red[8][32];

    float mx = -1e30f;
    for (int m = ty; m < MTOK; m += 8)
        mx = fmaxf(mx, Lb[(long long)m * SLOTS + s]);
    red[ty][tx] = mx;
    __syncthreads();
    if (ty == 0) {
        float v = red[0][tx];
        #pragma unroll
        for (int q = 1; q < 8; q++) v = fmaxf(v, red[q][tx]);
        red[0][tx] = v;
    }
    __syncthreads();
    mx = red[0][tx];
    __syncthreads();

    float sum = 0.f;
    for (int m = ty; m < MTOK; m += 8) {
        float e = __expf(Lb[(long long)m * SLOTS + s] - mx);
        Db[(long long)m * SLOTS + s] = e;
        sum += e;
    }
    red[ty][tx] = sum;
    __syncthreads();
    if (ty == 0) {
        float v = 0.f;
        #pragma unroll
        for (int q = 0; q < 8; q++) v += red[q][tx];
        red[0][tx] = v;
    }
    __syncthreads();
    float inv = 1.0f / red[0][tx];
    for (int m = ty; m < MTOK; m += 8)
        Db[(long long)m * SLOTS + s] *= inv;
}

__global__ void softmax_row_kernel(const float* __restrict__ L, float* __restrict__ Cout) {
    const long long row = blockIdx.x;
    const float* Lr = L + row * SLOTS;
    float* Cr = Cout + row * SLOTS;
    __shared__ float sm[32];
    const int t = threadIdx.x;

    float v[4];
    float mx = -1e30f;
    #pragma unroll
    for (int q = 0; q < 4; q++) { v[q] = Lr[t + q * 256]; mx = fmaxf(mx, v[q]); }
    mx = block_max256(mx, sm);
    float sum = 0.f;
    #pragma unroll
    for (int q = 0; q < 4; q++) { v[q] = __expf(v[q] - mx); sum += v[q]; }
    sum = block_sum256(sum, sm);
    float inv = 1.0f / sum;
    #pragma unroll
    for (int q = 0; q < 4; q++) Cr[t + q * 256] = v[q] * inv;
}

__global__ void ln_kernel(const float* __restrict__ Xs,
                          const float* __restrict__ g, const float* __restrict__ bta) {
    const long long row = blockIdx.x;
    const int b = (int)(row / SLOTS);
    const int s = (int)(row % SLOTS);
    const int n = s >> 4, p = s & 15;
    const float* xr = Xs + row * DIM;
    float* outr = g_Xn + ((long long)n * (BATCH * PP) + b * PP + p) * DIM;
    __shared__ float sm[32];
    const int t = threadIdx.x;

    float v[3];
    float ss = 0.f;
    #pragma unroll
    for (int q = 0; q < 3; q++) { v[q] = xr[t + q * 256]; ss += v[q]; }
    float mu = block_sum256(ss, sm) * (1.0f / DIM);
    float sv = 0.f;
    #pragma unroll
    for (int q = 0; q < 3; q++) { float d = v[q] - mu; sv += d * d; }
    float var = block_sum256(sv, sm) * (1.0f / DIM);
    float inv = rsqrtf(var + 1e-5f);
    #pragma unroll
    for (int q = 0; q < 3; q++) {
        int c = t + q * 256;
        outr[c] = (v[q] - mu) * inv * g[n * DIM + c] + bta[n * DIM + c];
    }
}

// ==================== launch ====================
extern "C" void kernel_launch(void* const* d_in, const int* in_sizes, int n_in,
                              void* d_out, int out_size) {
    const float* x    = (const float*)d_in[0];
    const float* phi  = (const float*)d_in[1];
    const float* ln_g = (const float*)d_in[2];
    const float* ln_b = (const float*)d_in[3];
    const float* w1   = (const float*)d_in[4];
    const float* b1   = (const float*)d_in[5];
    const float* w2   = (const float*)d_in[6];
    const float* b2   = (const float*)d_in[7];
    float* out = (float*)d_out;

    float *phin, *logits, *Dm, *Cmx, *Xs, *Xn, *Hb, *Ys;
    cudaGetSymbolAddress((void**)&phin,   g_phin);
    cudaGetSymbolAddress((void**)&logits, g_logits);
    cudaGetSymbolAddress((void**)&Dm,     g_Dmat);
    cudaGetSymbolAddress((void**)&Cmx,    g_Cmat);
    cudaGetSymbolAddress((void**)&Xs,     g_Xs);
    cudaGetSymbolAddress((void**)&Xn,     g_Xn);
    cudaGetSymbolAddress((void**)&Hb,     g_Hb);
    cudaGetSymbolAddress((void**)&Ys,     g_Ys);

    // 1) normalize phi over expert axis -> [s][d]
    phi_norm_kernel<<<(PP * DIM + 255) / 256, 256>>>(phi);

    // 2) logits[b] = X[b] (1024x768) * phin^T (768x1024)   [NT]
    tc_gemm<1, 0><<<dim3(MTOK / 128, SLOTS / 64, BATCH), 256>>>(
        x, phin, logits, nullptr,
        MTOK, SLOTS, DIM,
        (long long)MTOK * DIM, 0LL, (long long)MTOK * SLOTS, 0LL);

    // 3) dispatch D: softmax over m (columns); combine C: softmax over s (rows)
    softmax_col_kernel<<<dim3(SLOTS / 32, BATCH), 256>>>(logits, Dm);
    softmax_row_kernel<<<BATCH * MTOK, 256>>>(logits, Cmx);

    // 4) Xs[b] = D[b]^T (1024x1024) * X[b] (1024x768)   [TN]
    tc_gemm<2, 0><<<dim3(SLOTS / 128, DIM / 64, BATCH), 256>>>(
        Dm, x, Xs, nullptr,
        SLOTS, DIM, MTOK,
        (long long)MTOK * SLOTS, (long long)MTOK * DIM, (long long)SLOTS * DIM, 0LL);

    // 5) LayerNorm rows of Xs, scatter to expert-major [n][b*16+p][d]
    ln_kernel<<<BATCH * SLOTS, 256>>>(Xs, ln_g, ln_b);

    // 6) per-expert: H = GELU(Xn * W1 + b1)   [NN], z = expert
    tc_gemm<0, 2><<<dim3(1, HID / 64, NE), 256>>>(
        Xn, w1, Hb, b1,
        BATCH * PP, HID, DIM,
        (long long)BATCH * PP * DIM, (long long)DIM * HID,
        (long long)BATCH * PP * HID, (long long)HID);

    // 7) per-expert: Ys = H * W2 + b2, scattered back to [b][s][d]   [NN]
    tc_gemm<0, 3><<<dim3(1, DIM / 64, NE), 256>>>(
        Hb, w2, Ys, b2,
        BATCH * PP, DIM, HID,
        (long long)BATCH * PP * HID, (long long)HID * DIM,
        0LL, (long long)DIM);

    // 8) Y[b] = C[b] (1024x1024) * Ys[b] (1024x768)   [NN]
    tc_gemm<0, 0><<<dim3(MTOK / 128, DIM / 64, BATCH), 256>>>(
        Cmx, Ys, out, nullptr,
        MTOK, DIM, SLOTS,
        (long long)MTOK * SLOTS, (long long)SLOTS * DIM, (long long)MTOK * DIM, 0LL);
}

// round 10
// speedup vs baseline: 2.0214x; 1.4747x over previous
#include <cuda_runtime.h>
#include <cuda_bf16.h>
#include <math.h>
#include <stdint.h>

// Problem constants (fixed by the dataset)
constexpr int BATCH = 8;
constexpr int MTOK  = 1024;
constexpr int DIM   = 768;
constexpr int NE    = 64;
constexpr int PP    = 16;
constexpr int SLOTS = NE * PP;   // 1024
constexpr int HID   = 2 * DIM;   // 1536

// ---------------- scratch (static device memory) ----------
__device__ __align__(16) __nv_bfloat16 g_xh[BATCH * MTOK * DIM];
__device__ __align__(16) __nv_bfloat16 g_xl[BATCH * MTOK * DIM];
__device__ __align__(16) __nv_bfloat16 g_ph[SLOTS * DIM];
__device__ __align__(16) __nv_bfloat16 g_pl[SLOTS * DIM];
__device__ float g_logits[BATCH * MTOK * SLOTS];
__device__ float g_D[BATCH * MTOK * SLOTS];
__device__ __align__(16) __nv_bfloat16 g_Dth[BATCH * SLOTS * MTOK];
__device__ __align__(16) __nv_bfloat16 g_Dtl[BATCH * SLOTS * MTOK];
__device__ __align__(16) __nv_bfloat16 g_Ch[BATCH * MTOK * SLOTS];
__device__ __align__(16) __nv_bfloat16 g_Cl[BATCH * MTOK * SLOTS];
__device__ float g_Xs[BATCH * SLOTS * DIM];
__device__ __align__(16) __nv_bfloat16 g_Xnh[NE * BATCH * PP * DIM];
__device__ __align__(16) __nv_bfloat16 g_Xnl[NE * BATCH * PP * DIM];
__device__ __align__(16) __nv_bfloat16 g_Hbh[NE * BATCH * PP * HID];
__device__ __align__(16) __nv_bfloat16 g_Hbl[NE * BATCH * PP * HID];
__device__ __align__(16) __nv_bfloat16 g_Ysh[BATCH * SLOTS * DIM];
__device__ __align__(16) __nv_bfloat16 g_Ysl[BATCH * SLOTS * DIM];

// ==================== low-level helpers ====================
__device__ __forceinline__ uint32_t smem_u32(const void* p) {
    uint32_t a;
    asm("{ .reg .u64 t; cvta.to.shared.u64 t, %1; cvt.u32.u64 %0, t; }" : "=r"(a) : "l"(p));
    return a;
}
__device__ __forceinline__ void ldsm_x4(uint32_t* f, uint32_t addr) {
    asm volatile("ldmatrix.sync.aligned.m8n8.x4.shared.b16 {%0,%1,%2,%3}, [%4];"
        : "=r"(f[0]), "=r"(f[1]), "=r"(f[2]), "=r"(f[3]) : "r"(addr));
}
__device__ __forceinline__ void ldsm_x4t(uint32_t* f, uint32_t addr) {
    asm volatile("ldmatrix.sync.aligned.m8n8.x4.trans.shared.b16 {%0,%1,%2,%3}, [%4];"
        : "=r"(f[0]), "=r"(f[1]), "=r"(f[2]), "=r"(f[3]) : "r"(addr));
}
__device__ __forceinline__ void mma16816(float* c, const uint32_t* a, const uint32_t* b) {
    asm volatile("mma.sync.aligned.m16n8k16.row.col.f32.bf16.bf16.f32 "
        "{%0,%1,%2,%3}, {%4,%5,%6,%7}, {%8,%9}, {%0,%1,%2,%3};"
        : "+f"(c[0]), "+f"(c[1]), "+f"(c[2]), "+f"(c[3])
        : "r"(a[0]), "r"(a[1]), "r"(a[2]), "r"(a[3]), "r"(b[0]), "r"(b[1]));
}
__device__ __forceinline__ void cpasync16(uint32_t dst, const void* src) {
    asm volatile("cp.async.ca.shared.global [%0], [%1], 16;" :: "r"(dst), "l"(src));
}
__device__ __forceinline__ void cp_commit() { asm volatile("cp.async.commit_group;" ::: "memory"); }
template<int N> __device__ __forceinline__ void cp_wait() {
    asm volatile("cp.async.wait_group %0;" :: "n"(N) : "memory");
}
// split fp32 pair -> packed bf16x2 hi / lo
__device__ __forceinline__ void split2(float a, float b, uint32_t& h, uint32_t& l) {
    __nv_bfloat162 hh = __floats2bfloat162_rn(a, b);
    float2 f = __bfloat1622float2(hh);
    __nv_bfloat162 ll = __floats2bfloat162_rn(a - f.x, b - f.y);
    h = *(uint32_t*)&hh; l = *(uint32_t*)&ll;
}
// 64B-row tile swizzle (byte offset), rows of 32 bf16
__device__ __forceinline__ int swzA(int r, int byteCol) {
    return r * 64 + ((((byteCol >> 4) ^ ((r >> 1) & 3)) << 4)) + (byteCol & 15);
}
// 128B-row tile swizzle at 16B granularity (trans tiles [32k][64j])
__device__ __forceinline__ int swzT(int krow, int chunk) {
    return krow * 128 + ((chunk ^ (krow & 7)) << 4);
}

// ==================== tensor-core GEMM (bf16x3, cp.async pipelined) ==========
// A: bf16 hi/lo global, row-major [M][K] (K contiguous). 128x64 tile, K-chunk 32.
// BMODE: 0 = bf16 hi/lo [N][K] (K-contig, normal ldmatrix)
//        1 = bf16 hi/lo [K][N] (j-contig, ldmatrix.trans)
//        2 = fp32 [K][N] weights, inline convert (ldmatrix.trans)
// EPI:   0 = fp32 store; 2 = +bias, GELU, store bf16 hi/lo; 3 = +bias, store
//        bf16 hi/lo scattered per-expert (row r -> (r/16)*SLOTS + z*16 + r%16)
template<int BMODE, int EPI>
__global__ __launch_bounds__(256, 2)
void tc_gemm(const __nv_bfloat16* __restrict__ Ah, const __nv_bfloat16* __restrict__ Al,
             const void* __restrict__ Bp, const __nv_bfloat16* __restrict__ Blo,
             float* __restrict__ Cf,
             __nv_bfloat16* __restrict__ Oh, __nv_bfloat16* __restrict__ Ol,
             const float* __restrict__ bias,
             int Mq, int Nq, int Kq,
             long long sA, long long sB, long long sC, long long sBias)
{
    __shared__ __align__(128) char bufAh[2][8192];
    __shared__ __align__(128) char bufAl[2][8192];
    __shared__ __align__(128) char bufBh[2][4096];
    __shared__ __align__(128) char bufBl[2][4096];

    const int t = threadIdx.x;
    const int wid = t >> 5;
    const int lane = t & 31;
    const int warp_m = wid >> 1;     // 0..3
    const int warp_n = wid & 1;      // 0..1
    const int i0 = blockIdx.x * 128;
    const int j0 = blockIdx.y * 64;
    const int bz = blockIdx.z;

    const __nv_bfloat16* Abh = Ah + (long long)bz * sA;
    const __nv_bfloat16* Abl = Al + (long long)bz * sA;
    const __nv_bfloat16* Bbh = (BMODE < 2) ? (const __nv_bfloat16*)Bp + (long long)bz * sB : nullptr;
    const __nv_bfloat16* Bbl = (BMODE < 2) ? Blo + (long long)bz * sB : nullptr;
    const float*         Wb  = (BMODE == 2) ? (const float*)Bp + (long long)bz * sB : nullptr;

    uint32_t sAh32[2], sAl32[2], sBh32[2], sBl32[2];
    #pragma unroll
    for (int q = 0; q < 2; q++) {
        sAh32[q] = smem_u32(bufAh[q]); sAl32[q] = smem_u32(bufAl[q]);
        sBh32[q] = smem_u32(bufBh[q]); sBl32[q] = smem_u32(bufBl[q]);
    }

    // -------- copy helpers --------
    auto copyTiles = [&](int it, int buf) {
        const int k0 = it * 32;
        // A tile: 128 rows x 32 k (hi & lo): 512 16B-chunks each
        #pragma unroll
        for (int q = 0; q < 2; q++) {
            int pos = t * 2 + q;              // 0..511
            int row = pos >> 2, ch = pos & 3;
            long long g = (long long)(i0 + row) * Kq + k0 + ch * 8;
            int d = swzA(row, ch * 16);
            cpasync16(sAh32[buf] + d, Abh + g);
            cpasync16(sAl32[buf] + d, Abl + g);
        }
        if (BMODE == 0) {
            // B tile [64 n][32 k]: 256 chunks each
            int row = t >> 2, ch = t & 3;
            long long g = (long long)(j0 + row) * Kq + k0 + ch * 8;
            int d = swzA(row, ch * 16);
            cpasync16(sBh32[buf] + d, Bbh + g);
            cpasync16(sBl32[buf] + d, Bbl + g);
        } else if (BMODE == 1) {
            // B tile [32 k][64 j]: 256 chunks each
            int krow = t >> 3, ch = t & 7;
            long long g = (long long)(k0 + krow) * Nq + j0 + ch * 8;
            int d = swzT(krow, ch);
            cpasync16(sBh32[buf] + d, Bbh + g);
            cpasync16(sBl32[buf] + d, Bbl + g);
        }
    };
    auto wload = [&](int it, int buf) {   // BMODE==2 only: fp32 W -> bf16 hi/lo tile
        const int k0 = it * 32;
        #pragma unroll
        for (int q = 0; q < 2; q++) {
            int f4 = t * 2 + q;               // 0..511
            int krow = f4 >> 4, c4 = f4 & 15, j = c4 * 4;
            float4 v = *(const float4*)&Wb[(long long)(k0 + krow) * Nq + j0 + j];
            uint32_t h0, l0, h1, l1;
            split2(v.x, v.y, h0, l0);
            split2(v.z, v.w, h1, l1);
            int d = swzT(krow, c4 >> 1) + (c4 & 1) * 8;
            uint2 hv; hv.x = h0; hv.y = h1;
            uint2 lv; lv.x = l0; lv.y = l1;
            *(uint2*)(bufBh[buf] + d) = hv;
            *(uint2*)(bufBl[buf] + d) = lv;
        }
    };

    // -------- fragment offsets --------
    int aoff[2][2];
    #pragma unroll
    for (int sm = 0; sm < 2; sm++)
        #pragma unroll
        for (int ks = 0; ks < 2; ks++)
            aoff[sm][ks] = swzA(warp_m * 32 + sm * 16 + (lane & 15),
                                ks * 32 + ((lane >> 4) << 4));
    int boff[2][2];
    if (BMODE == 0) {
        #pragma unroll
        for (int pr = 0; pr < 2; pr++)
            #pragma unroll
            for (int ks = 0; ks < 2; ks++)
                boff[pr][ks] = swzA(warp_n * 32 + pr * 16 + ((lane >> 4) << 3) + (lane & 7),
                                    ks * 32 + (((lane >> 3) & 1) << 4));
    } else {
        int g = lane >> 3, r = lane & 7;
        #pragma unroll
        for (int pr = 0; pr < 2; pr++)
            #pragma unroll
            for (int ks = 0; ks < 2; ks++) {
                int k = ks * 16 + (g & 1) * 8 + r;
                int ncol = warp_n * 32 + pr * 16 + (g >> 1) * 8;
                boff[pr][ks] = swzT(k, ncol >> 3);
            }
    }

    float acc[2][4][4];
    #pragma unroll
    for (int a = 0; a < 2; a++)
        #pragma unroll
        for (int b = 0; b < 4; b++)
            #pragma unroll
            for (int c = 0; c < 4; c++) acc[a][b][c] = 0.f;

    const int n_iter = Kq >> 5;

    // -------- prologue --------
    copyTiles(0, 0); cp_commit();
    copyTiles(1, 1); cp_commit();
    if (BMODE == 2) wload(0, 0);

    // -------- main loop --------
    for (int it = 0; it < n_iter; it++) {
        const int buf = it & 1;
        if (it + 1 < n_iter) cp_wait<1>(); else cp_wait<0>();
        __syncthreads();

        #pragma unroll
        for (int ks = 0; ks < 2; ks++) {
            uint32_t a_hi[2][4], a_lo[2][4], b_hi[4][2], b_lo[4][2];
            #pragma unroll
            for (int sm = 0; sm < 2; sm++) {
                ldsm_x4(a_hi[sm], sAh32[buf] + aoff[sm][ks]);
                ldsm_x4(a_lo[sm], sAl32[buf] + aoff[sm][ks]);
            }
            #pragma unroll
            for (int pr = 0; pr < 2; pr++) {
                if (BMODE == 0) {
                    ldsm_x4(&b_hi[pr * 2][0], sBh32[buf] + boff[pr][ks]);
                    ldsm_x4(&b_lo[pr * 2][0], sBl32[buf] + boff[pr][ks]);
                } else {
                    ldsm_x4t(&b_hi[pr * 2][0], sBh32[buf] + boff[pr][ks]);
                    ldsm_x4t(&b_lo[pr * 2][0], sBl32[buf] + boff[pr][ks]);
                }
            }
            #pragma unroll
            for (int sm = 0; sm < 2; sm++)
                #pragma unroll
                for (int sn = 0; sn < 4; sn++) {
                    mma16816(acc[sm][sn], a_hi[sm], b_hi[sn]);
                    mma16816(acc[sm][sn], a_hi[sm], b_lo[sn]);
                    mma16816(acc[sm][sn], a_lo[sm], b_hi[sn]);
                }
        }

        if (BMODE == 2 && it + 1 < n_iter) wload(it + 1, (it + 1) & 1);
        __syncthreads();
        if (it + 2 < n_iter) { copyTiles(it + 2, buf); cp_commit(); }
    }

    // -------- epilogue --------
    #pragma unroll
    for (int sm = 0; sm < 2; sm++) {
        #pragma unroll
        for (int half = 0; half < 2; half++) {
            int r = i0 + warp_m * 32 + sm * 16 + (lane >> 2) + half * 8;
            #pragma unroll
            for (int sn = 0; sn < 4; sn++) {
                int c = j0 + warp_n * 32 + sn * 8 + (lane & 3) * 2;
                float v0 = acc[sm][sn][half * 2 + 0];
                float v1 = acc[sm][sn][half * 2 + 1];
                if (EPI >= 2) {
                    v0 += bias[(long long)bz * sBias + c];
                    v1 += bias[(long long)bz * sBias + c + 1];
                }
                if (EPI == 2) {
                    v0 = 0.5f * v0 * (1.0f + erff(v0 * 0.70710678118654752f));
                    v1 = 0.5f * v1 * (1.0f + erff(v1 * 0.70710678118654752f));
                }
                if (EPI == 0) {
                    float2 st; st.x = v0; st.y = v1;
                    *(float2*)&Cf[(long long)bz * sC + (long long)r * Nq + c] = st;
                } else {
                    long long rr;
                    if (EPI == 3)
                        rr = (long long)(r >> 4) * SLOTS + (long long)bz * PP + (r & 15);
                    else
                        rr = (long long)bz * (sC / Nq) + r;   // row within output
                    long long idx = (EPI == 3) ? rr * Nq + c
                                               : (long long)bz * sC + (long long)r * Nq + c;
                    uint32_t h, l;
                    split2(v0, v1, h, l);
                    *(uint32_t*)&Oh[idx] = h;
                    *(uint32_t*)&Ol[idx] = l;
                }
            }
        }
    }
}

// ==================== small kernels ====================
__device__ __forceinline__ float block_sum256(float v, float* sm) {
    int t = threadIdx.x;
    #pragma unroll
    for (int o = 16; o > 0; o >>= 1) v += __shfl_xor_sync(0xffffffffu, v, o);
    if ((t & 31) == 0) sm[t >> 5] = v;
    __syncthreads();
    if (t < 8) {
        float w = sm[t];
        #pragma unroll
        for (int o = 4; o > 0; o >>= 1) w += __shfl_xor_sync(0xffu, w, o);
        if (t == 0) sm[0] = w;
    }
    __syncthreads();
    v = sm[0];
    __syncthreads();
    return v;
}
__device__ __forceinline__ float block_max256(float v, float* sm) {
    int t = threadIdx.x;
    #pragma unroll
    for (int o = 16; o > 0; o >>= 1) v = fmaxf(v, __shfl_xor_sync(0xffffffffu, v, o));
    if ((t & 31) == 0) sm[t >> 5] = v;
    __syncthreads();
    if (t < 8) {
        float w = sm[t];
        #pragma unroll
        for (int o = 4; o > 0; o >>= 1) w = fmaxf(w, __shfl_xor_sync(0xffu, w, o));
        if (t == 0) sm[0] = w;
    }
    __syncthreads();
    v = sm[0];
    __syncthreads();
    return v;
}

// split x -> bf16 hi/lo
__global__ void split_kernel(const float* __restrict__ src,
                             __nv_bfloat16* __restrict__ h, __nv_bfloat16* __restrict__ l,
                             int n4) {
    int i = blockIdx.x * blockDim.x + threadIdx.x;
    if (i >= n4) return;
    float4 v = *(const float4*)&src[i * 4];
    uint32_t h0, l0, h1, l1;
    split2(v.x, v.y, h0, l0);
    split2(v.z, v.w, h1, l1);
    uint2 hv; hv.x = h0; hv.y = h1;
    uint2 lv; lv.x = l0; lv.y = l1;
    *(uint2*)&h[i * 4] = hv;
    *(uint2*)&l[i * 4] = lv;
}

// normalize phi over expert axis -> bf16 hi/lo [s][d]
__global__ void phi_norm_kernel(const float* __restrict__ phi) {
    int t = blockIdx.x * blockDim.x + threadIdx.x;
    if (t >= PP * DIM) return;
    float ss = 0.f;
    #pragma unroll 4
    for (int n = 0; n < NE; n++) {
        float v = phi[n * PP * DIM + t];
        ss += v * v;
    }
    float inv = rsqrtf(ss + 1e-6f);
    #pragma unroll 4
    for (int n = 0; n < NE; n++) {
        float v = phi[n * PP * DIM + t] * inv;
        __nv_bfloat16 h = __float2bfloat16_rn(v);
        g_ph[n * PP * DIM + t] = h;
        g_pl[n * PP * DIM + t] = __float2bfloat16_rn(v - __bfloat162float(h));
    }
}

// softmax over tokens m -> fp32 D [b][m][s]
__global__ void softmax_col_kernel(const float* __restrict__ L, float* __restrict__ Dout) {
    const int tx = threadIdx.x & 31, ty = threadIdx.x >> 5;
    const int s = blockIdx.x * 32 + tx;
    const float* Lb = L + (long long)blockIdx.y * MTOK * SLOTS;
    float* Db = Dout + (long long)blockIdx.y * MTOK * SLOTS;
    __shared__ float red[8][32];

    float mx = -1e30f;
    for (int m = ty; m < MTOK; m += 8)
        mx = fmaxf(mx, Lb[(long long)m * SLOTS + s]);
    red[ty][tx] = mx;
    __syncthreads();
    if (ty == 0) {
        float v = red[0][tx];
        #pragma unroll
        for (int q = 1; q < 8; q++) v = fmaxf(v, red[q][tx]);
        red[0][tx] = v;
    }
    __syncthreads();
    mx = red[0][tx];
    __syncthreads();

    float sum = 0.f;
    for (int m = ty; m < MTOK; m += 8) {
        float e = __expf(Lb[(long long)m * SLOTS + s] - mx);
        Db[(long long)m * SLOTS + s] = e;
        sum += e;
    }
    red[ty][tx] = sum;
    __syncthreads();
    if (ty == 0) {
        float v = 0.f;
        #pragma unroll
        for (int q = 0; q < 8; q++) v += red[q][tx];
        red[0][tx] = v;
    }
    __syncthreads();
    float inv = 1.0f / red[0][tx];
    for (int m = ty; m < MTOK; m += 8)
        Db[(long long)m * SLOTS + s] *= inv;
}

// transpose + split D [b][m][s] -> Dt hi/lo [b][s][m]
__global__ void dtrans_kernel(const float* __restrict__ D) {
    __shared__ float tile[32][33];
    const int s0 = blockIdx.x * 32, m0 = blockIdx.y * 32, b = blockIdx.z;
    const int tx = threadIdx.x & 31, ty = threadIdx.x >> 5;
    #pragma unroll
    for (int q = 0; q < 4; q++) {
        int m = m0 + ty + q * 8;
        tile[ty + q * 8][tx] = D[((long long)b * MTOK + m) * SLOTS + s0 + tx];
    }
    __syncthreads();
    #pragma unroll
    for (int q = 0; q < 4; q++) {
        int s = s0 + ty + q * 8;
        float v = tile[tx][ty + q * 8];
        long long o = ((long long)b * SLOTS + s) * MTOK + m0 + tx;
        __nv_bfloat16 h = __float2bfloat16_rn(v);
        g_Dth[o] = h;
        g_Dtl[o] = __float2bfloat16_rn(v - __bfloat162float(h));
    }
}

// softmax over slots s -> bf16 hi/lo C [b*m][s]
__global__ void softmax_row_kernel(const float* __restrict__ L) {
    const long long row = blockIdx.x;
    const float* Lr = L + row * SLOTS;
    __shared__ float sm[32];
    const int t = threadIdx.x;

    float v[4];
    float mx = -1e30f;
    #pragma unroll
    for (int q = 0; q < 4; q++) { v[q] = Lr[t + q * 256]; mx = fmaxf(mx, v[q]); }
    mx = block_max256(mx, sm);
    float sum = 0.f;
    #pragma unroll
    for (int q = 0; q < 4; q++) { v[q] = __expf(v[q] - mx); sum += v[q]; }
    sum = block_sum256(sum, sm);
    float inv = 1.0f / sum;
    #pragma unroll
    for (int q = 0; q < 4; q++) {
        float c = v[q] * inv;
        __nv_bfloat16 h = __float2bfloat16_rn(c);
        g_Ch[row * SLOTS + t + q * 256] = h;
        g_Cl[row * SLOTS + t + q * 256] = __float2bfloat16_rn(c - __bfloat162float(h));
    }
}

// LayerNorm rows of Xs -> bf16 hi/lo, expert-major [n][b*16+p][d]
__global__ void ln_kernel(const float* __restrict__ Xs,
                          const float* __restrict__ g, const float* __restrict__ bta) {
    const long long row = blockIdx.x;
    const int b = (int)(row / SLOTS);
    const int s = (int)(row % SLOTS);
    const int n = s >> 4, p = s & 15;
    const float* xr = Xs + row * DIM;
    long long obase = ((long long)n * (BATCH * PP) + b * PP + p) * DIM;
    __shared__ float sm[32];
    const int t = threadIdx.x;

    float v[3];
    float ss = 0.f;
    #pragma unroll
    for (int q = 0; q < 3; q++) { v[q] = xr[t + q * 256]; ss += v[q]; }
    float mu = block_sum256(ss, sm) * (1.0f / DIM);
    float sv = 0.f;
    #pragma unroll
    for (int q = 0; q < 3; q++) { float d = v[q] - mu; sv += d * d; }
    float var = block_sum256(sv, sm) * (1.0f / DIM);
    float inv = rsqrtf(var + 1e-5f);
    #pragma unroll
    for (int q = 0; q < 3; q++) {
        int c = t + q * 256;
        float o = (v[q] - mu) * inv * g[n * DIM + c] + bta[n * DIM + c];
        __nv_bfloat16 h = __float2bfloat16_rn(o);
        g_Xnh[obase + c] = h;
        g_Xnl[obase + c] = __float2bfloat16_rn(o - __bfloat162float(h));
    }
}

// ==================== launch ====================
extern "C" void kernel_launch(void* const* d_in, const int* in_sizes, int n_in,
                              void* d_out, int out_size) {
    const float* x    = (const float*)d_in[0];
    const float* phi  = (const float*)d_in[1];
    const float* ln_g = (const float*)d_in[2];
    const float* ln_b = (const float*)d_in[3];
    const float* w1   = (const float*)d_in[4];
    const float* b1   = (const float*)d_in[5];
    const float* w2   = (const float*)d_in[6];
    const float* b2   = (const float*)d_in[7];
    float* out = (float*)d_out;

    __nv_bfloat16 *xh, *xl, *ph, *pl, *Dth, *Dtl, *Ch, *Cl, *Xnh, *Xnl, *Hbh, *Hbl, *Ysh, *Ysl;
    float *logits, *Dm, *Xs;
    cudaGetSymbolAddress((void**)&xh, g_xh);   cudaGetSymbolAddress((void**)&xl, g_xl);
    cudaGetSymbolAddress((void**)&ph, g_ph);   cudaGetSymbolAddress((void**)&pl, g_pl);
    cudaGetSymbolAddress((void**)&logits, g_logits);
    cudaGetSymbolAddress((void**)&Dm, g_D);
    cudaGetSymbolAddress((void**)&Dth, g_Dth); cudaGetSymbolAddress((void**)&Dtl, g_Dtl);
    cudaGetSymbolAddress((void**)&Ch, g_Ch);   cudaGetSymbolAddress((void**)&Cl, g_Cl);
    cudaGetSymbolAddress((void**)&Xs, g_Xs);
    cudaGetSymbolAddress((void**)&Xnh, g_Xnh); cudaGetSymbolAddress((void**)&Xnl, g_Xnl);
    cudaGetSymbolAddress((void**)&Hbh, g_Hbh); cudaGetSymbolAddress((void**)&Hbl, g_Hbl);
    cudaGetSymbolAddress((void**)&Ysh, g_Ysh); cudaGetSymbolAddress((void**)&Ysl, g_Ysl);

    // 1) split x; normalize+split phi
    split_kernel<<<(BATCH * MTOK * DIM / 4 + 255) / 256, 256>>>(x, xh, xl, BATCH * MTOK * DIM / 4);
    phi_norm_kernel<<<(PP * DIM + 255) / 256, 256>>>(phi);

    // 2) logits[b] = X[b] * phin^T   (A=x K-contig, B=phin K-contig)
    tc_gemm<0, 0><<<dim3(MTOK / 128, SLOTS / 64, BATCH), 256>>>(
        xh, xl, ph, pl, logits, nullptr, nullptr, nullptr,
        MTOK, SLOTS, DIM,
        (long long)MTOK * DIM, 0LL, (long long)MTOK * SLOTS, 0LL);

    // 3) softmaxes: D (fp32, then transposed+split), C (bf16 pair)
    softmax_col_kernel<<<dim3(SLOTS / 32, BATCH), 256>>>(logits, Dm);
    dtrans_kernel<<<dim3(SLOTS / 32, MTOK / 32, BATCH), 256>>>(Dm);
    softmax_row_kernel<<<BATCH * MTOK, 256>>>(logits);

    // 4) Xs[b][s][d] = sum_m Dt[s][m] * x[m][d]   (A=Dt K-contig, B=x KxN trans)
    tc_gemm<1, 0><<<dim3(SLOTS / 128, DIM / 64, BATCH), 256>>>(
        Dth, Dtl, xh, xl, Xs, nullptr, nullptr, nullptr,
        SLOTS, DIM, MTOK,
        (long long)SLOTS * MTOK, (long long)MTOK * DIM, (long long)SLOTS * DIM, 0LL);

    // 5) LayerNorm -> expert-major bf16 pair
    ln_kernel<<<BATCH * SLOTS, 256>>>(Xs, ln_g, ln_b);

    // 6) per-expert H = GELU(Xn*W1 + b1) -> bf16 pair
    tc_gemm<2, 2><<<dim3(1, HID / 64, NE), 256>>>(
        Xnh, Xnl, w1, nullptr, nullptr, Hbh, Hbl, b1,
        BATCH * PP, HID, DIM,
        (long long)BATCH * PP * DIM, (long long)DIM * HID,
        (long long)BATCH * PP * HID, (long long)HID);

    // 7) per-expert Ys = H*W2 + b2, scattered to [b][s][d] bf16 pair
    tc_gemm<2, 3><<<dim3(1, DIM / 64, NE), 256>>>(
        Hbh, Hbl, w2, nullptr, nullptr, Ysh, Ysl, b2,
        BATCH * PP, DIM, HID,
        (long long)BATCH * PP * HID, (long long)HID * DIM,
        0LL, (long long)DIM);

    // 8) Y[b] = C[b] * Ys[b]   (A=C K-contig, B=Ys KxN trans)
    tc_gemm<1, 0><<<dim3(MTOK / 128, DIM / 64, BATCH), 256>>>(
        Ch, Cl, Ysh, Ysl, out, nullptr, nullptr, nullptr,
        MTOK, DIM, SLOTS,
        (long long)MTOK * SLOTS, (long long)SLOTS * DIM, (long long)MTOK * DIM, 0LL);
}

// round 11
// speedup vs baseline: 2.0624x; 1.0203x over previous
#include <cuda_runtime.h>
#include <cuda_bf16.h>
#include <math.h>
#include <stdint.h>

// Problem constants (fixed by the dataset)
constexpr int BATCH = 8;
constexpr int MTOK  = 1024;
constexpr int DIM   = 768;
constexpr int NE    = 64;
constexpr int PP    = 16;
constexpr int SLOTS = NE * PP;   // 1024
constexpr int HID   = 2 * DIM;   // 1536

// ---------------- scratch (static device memory) ----------
__device__ __align__(16) __nv_bfloat16 g_xh[BATCH * MTOK * DIM];
__device__ __align__(16) __nv_bfloat16 g_xl[BATCH * MTOK * DIM];
__device__ __align__(16) __nv_bfloat16 g_ph[SLOTS * DIM];
__device__ __align__(16) __nv_bfloat16 g_pl[SLOTS * DIM];
__device__ float g_logits[BATCH * MTOK * SLOTS];
__device__ float g_D[BATCH * MTOK * SLOTS];
__device__ __align__(16) __nv_bfloat16 g_Dth[BATCH * SLOTS * MTOK];
__device__ __align__(16) __nv_bfloat16 g_Dtl[BATCH * SLOTS * MTOK];
__device__ __align__(16) __nv_bfloat16 g_Ch[BATCH * MTOK * SLOTS];
__device__ __align__(16) __nv_bfloat16 g_Cl[BATCH * MTOK * SLOTS];
__device__ float g_Xs[BATCH * SLOTS * DIM];
__device__ __align__(16) __nv_bfloat16 g_Xnh[NE * BATCH * PP * DIM];
__device__ __align__(16) __nv_bfloat16 g_Xnl[NE * BATCH * PP * DIM];
__device__ __align__(16) __nv_bfloat16 g_Hbh[NE * BATCH * PP * HID];
__device__ __align__(16) __nv_bfloat16 g_Hbl[NE * BATCH * PP * HID];
__device__ __align__(16) __nv_bfloat16 g_Ysh[BATCH * SLOTS * DIM];
__device__ __align__(16) __nv_bfloat16 g_Ysl[BATCH * SLOTS * DIM];

// ==================== low-level helpers ====================
__device__ __forceinline__ uint32_t smem_u32(const void* p) {
    uint32_t a;
    asm("{ .reg .u64 t; cvta.to.shared.u64 t, %1; cvt.u32.u64 %0, t; }" : "=r"(a) : "l"(p));
    return a;
}
__device__ __forceinline__ void ldsm_x4(uint32_t* f, uint32_t addr) {
    asm volatile("ldmatrix.sync.aligned.m8n8.x4.shared.b16 {%0,%1,%2,%3}, [%4];"
        : "=r"(f[0]), "=r"(f[1]), "=r"(f[2]), "=r"(f[3]) : "r"(addr));
}
__device__ __forceinline__ void ldsm_x4t(uint32_t* f, uint32_t addr) {
    asm volatile("ldmatrix.sync.aligned.m8n8.x4.trans.shared.b16 {%0,%1,%2,%3}, [%4];"
        : "=r"(f[0]), "=r"(f[1]), "=r"(f[2]), "=r"(f[3]) : "r"(addr));
}
__device__ __forceinline__ void mma16816(float* c, const uint32_t* a, const uint32_t* b) {
    asm volatile("mma.sync.aligned.m16n8k16.row.col.f32.bf16.bf16.f32 "
        "{%0,%1,%2,%3}, {%4,%5,%6,%7}, {%8,%9}, {%0,%1,%2,%3};"
        : "+f"(c[0]), "+f"(c[1]), "+f"(c[2]), "+f"(c[3])
        : "r"(a[0]), "r"(a[1]), "r"(a[2]), "r"(a[3]), "r"(b[0]), "r"(b[1]));
}
__device__ __forceinline__ void cpasync16(uint32_t dst, const void* src) {
    asm volatile("cp.async.ca.shared.global [%0], [%1], 16;" :: "r"(dst), "l"(src));
}
__device__ __forceinline__ void cp_commit() { asm volatile("cp.async.commit_group;" ::: "memory"); }
template<int N> __device__ __forceinline__ void cp_wait() {
    asm volatile("cp.async.wait_group %0;" :: "n"(N) : "memory");
}
// split fp32 pair -> packed bf16x2 hi / lo
__device__ __forceinline__ void split2(float a, float b, uint32_t& h, uint32_t& l) {
    __nv_bfloat162 hh = __floats2bfloat162_rn(a, b);
    float2 f = __bfloat1622float2(hh);
    __nv_bfloat162 ll = __floats2bfloat162_rn(a - f.x, b - f.y);
    h = *(uint32_t*)&hh; l = *(uint32_t*)&ll;
}
// 64B-row tile swizzle (byte offset), rows of 32 bf16 (A tiles, [rows][32k])
__device__ __forceinline__ int swzA(int r, int byteCol) {
    return r * 64 + ((((byteCol >> 4) ^ ((r >> 1) & 3)) << 4)) + (byteCol & 15);
}
// 256B-row trans-tile swizzle at 16B granularity ([32k][128j], chunk 0..15)
__device__ __forceinline__ int swzT2(int krow, int chunk) {
    return krow * 256 + ((chunk ^ (krow & 7)) << 4);
}

// smem layout: 3 stages x 32KB: [Ah 8K][Al 8K][Bh 8K][Bl 8K]
constexpr int ST_SZ   = 32768;
constexpr int OFF_AL  = 8192;
constexpr int OFF_BH  = 16384;
constexpr int OFF_BL  = 24576;
constexpr int SMEM_SZ = 3 * ST_SZ;   // 98304

// ==================== tensor-core GEMM (bf16x3, 3-stage cp.async) ===========
// A: bf16 hi/lo global, row-major [M][K]. Block tile 128x128, K-chunk 32.
// BMODE: 0 = bf16 hi/lo [N][K] (K-contig, normal ldmatrix)
//        1 = bf16 hi/lo [K][N] (j-contig, ldmatrix.trans)
//        2 = fp32 [K][N] weights, inline convert (ldmatrix.trans)
// EPI:   0 = fp32 store; 2 = +bias, GELU, store bf16 hi/lo; 3 = +bias, store
//        bf16 hi/lo scattered per-expert (row r -> (r/16)*SLOTS + z*16 + r%16)
template<int BMODE, int EPI>
__global__ __launch_bounds__(256, 1)
void tc_gemm(const __nv_bfloat16* __restrict__ Ah, const __nv_bfloat16* __restrict__ Al,
             const void* __restrict__ Bp, const __nv_bfloat16* __restrict__ Blo,
             float* __restrict__ Cf,
             __nv_bfloat16* __restrict__ Oh, __nv_bfloat16* __restrict__ Ol,
             const float* __restrict__ bias,
             int Mq, int Nq, int Kq,
             long long sA, long long sB, long long sC, long long sBias)
{
    extern __shared__ __align__(128) char smem[];
    const uint32_t sb = smem_u32(smem);

    const int t = threadIdx.x;
    const int wid = t >> 5;
    const int lane = t & 31;
    const int warp_m = wid >> 1;     // 0..3  (32 rows each)
    const int warp_n = wid & 1;      // 0..1  (64 cols each)
    const int i0 = blockIdx.x * 128;
    const int j0 = blockIdx.y * 128;
    const int bz = blockIdx.z;

    const __nv_bfloat16* Abh = Ah + (long long)bz * sA;
    const __nv_bfloat16* Abl = Al + (long long)bz * sA;
    const __nv_bfloat16* Bbh = (BMODE < 2) ? (const __nv_bfloat16*)Bp + (long long)bz * sB : nullptr;
    const __nv_bfloat16* Bbl = (BMODE < 2) ? Blo + (long long)bz * sB : nullptr;
    const float*         Wb  = (BMODE == 2) ? (const float*)Bp + (long long)bz * sB : nullptr;

    // -------- copy helpers --------
    auto copyTiles = [&](int it, int st) {
        const int k0 = it * 32;
        const uint32_t base = sb + st * ST_SZ;
        // A tile: 128 rows x 32 k, hi & lo: 512 16B-chunks each
        #pragma unroll
        for (int q = 0; q < 2; q++) {
            int pos = t * 2 + q;              // 0..511
            int row = pos >> 2, ch = pos & 3;
            long long g = (long long)(i0 + row) * Kq + k0 + ch * 8;
            int d = swzA(row, ch * 16);
            cpasync16(base + d, Abh + g);
            cpasync16(base + OFF_AL + d, Abl + g);
        }
        if (BMODE == 0) {
            // B tile [128 n][32 k]: 512 chunks each
            #pragma unroll
            for (int q = 0; q < 2; q++) {
                int pos = t * 2 + q;
                int row = pos >> 2, ch = pos & 3;
                long long g = (long long)(j0 + row) * Kq + k0 + ch * 8;
                int d = swzA(row, ch * 16);
                cpasync16(base + OFF_BH + d, Bbh + g);
                cpasync16(base + OFF_BL + d, Bbl + g);
            }
        } else if (BMODE == 1) {
            // B tile [32 k][128 j]: 512 chunks each (16 chunks per k-row)
            #pragma unroll
            for (int q = 0; q < 2; q++) {
                int pos = t * 2 + q;
                int krow = pos >> 4, ch = pos & 15;
                long long g = (long long)(k0 + krow) * Nq + j0 + ch * 8;
                int d = swzT2(krow, ch);
                cpasync16(base + OFF_BH + d, Bbh + g);
                cpasync16(base + OFF_BL + d, Bbl + g);
            }
        }
    };
    auto wload = [&](int it, int st) {   // BMODE==2: fp32 W [32k][128j] -> bf16 hi/lo
        const int k0 = it * 32;
        char* base = smem + st * ST_SZ;
        #pragma unroll
        for (int q = 0; q < 4; q++) {
            int f4 = t * 4 + q;               // 0..1023
            int krow = f4 >> 5, c4 = f4 & 31, j = c4 * 4;
            float4 v = *(const float4*)&Wb[(long long)(k0 + krow) * Nq + j0 + j];
            uint32_t h0, l0, h1, l1;
            split2(v.x, v.y, h0, l0);
            split2(v.z, v.w, h1, l1);
            int d = swzT2(krow, c4 >> 1) + (c4 & 1) * 8;
            uint2 hv; hv.x = h0; hv.y = h1;
            uint2 lv; lv.x = l0; lv.y = l1;
            *(uint2*)(base + OFF_BH + d) = hv;
            *(uint2*)(base + OFF_BL + d) = lv;
        }
    };

    // -------- fragment offsets --------
    int aoff[2][2];
    #pragma unroll
    for (int sm = 0; sm < 2; sm++)
        #pragma unroll
        for (int ks = 0; ks < 2; ks++)
            aoff[sm][ks] = swzA(warp_m * 32 + sm * 16 + (lane & 15),
                                ks * 32 + ((lane >> 4) << 4));
    int boff[4][2];   // 4 pair-groups of 16 cols each (8 n-subtiles)
    if (BMODE == 0) {
        #pragma unroll
        for (int pr = 0; pr < 4; pr++)
            #pragma unroll
            for (int ks = 0; ks < 2; ks++)
                boff[pr][ks] = swzA(warp_n * 64 + pr * 16 + ((lane >> 4) << 3) + (lane & 7),
                                    ks * 32 + (((lane >> 3) & 1) << 4));
    } else {
        int g = lane >> 3, r = lane & 7;
        #pragma unroll
        for (int pr = 0; pr < 4; pr++)
            #pragma unroll
            for (int ks = 0; ks < 2; ks++) {
                int k = ks * 16 + (g & 1) * 8 + r;
                int ncol = warp_n * 64 + pr * 16 + (g >> 1) * 8;
                boff[pr][ks] = swzT2(k, ncol >> 3);
            }
    }

    float acc[2][8][4];
    #pragma unroll
    for (int a = 0; a < 2; a++)
        #pragma unroll
        for (int b = 0; b < 8; b++)
            #pragma unroll
            for (int c = 0; c < 4; c++) acc[a][b][c] = 0.f;

    const int n_iter = Kq >> 5;

    // -------- prologue: fill 3 stages --------
    copyTiles(0, 0); cp_commit();
    copyTiles(1, 1); cp_commit();
    copyTiles(2, 2); cp_commit();
    if (BMODE == 2) wload(0, 0);

    // -------- main loop --------
    for (int it = 0; it < n_iter; it++) {
        const int st = it % 3;
        const uint32_t base = sb + st * ST_SZ;
        if (it + 3 <= n_iter) cp_wait<2>();
        else if (it + 2 == n_iter) cp_wait<1>();
        else cp_wait<0>();
        __syncthreads();

        #pragma unroll
        for (int ks = 0; ks < 2; ks++) {
            uint32_t a_hi[2][4], a_lo[2][4], b_hi[8][2], b_lo[8][2];
            #pragma unroll
            for (int sm = 0; sm < 2; sm++) {
                ldsm_x4(a_hi[sm], base + aoff[sm][ks]);
                ldsm_x4(a_lo[sm], base + OFF_AL + aoff[sm][ks]);
            }
            #pragma unroll
            for (int pr = 0; pr < 4; pr++) {
                if (BMODE == 0) {
                    ldsm_x4(&b_hi[pr * 2][0], base + OFF_BH + boff[pr][ks]);
                    ldsm_x4(&b_lo[pr * 2][0], base + OFF_BL + boff[pr][ks]);
                } else {
                    ldsm_x4t(&b_hi[pr * 2][0], base + OFF_BH + boff[pr][ks]);
                    ldsm_x4t(&b_lo[pr * 2][0], base + OFF_BL + boff[pr][ks]);
                }
            }
            #pragma unroll
            for (int sm = 0; sm < 2; sm++)
                #pragma unroll
                for (int sn = 0; sn < 8; sn++) {
                    mma16816(acc[sm][sn], a_hi[sm], b_hi[sn]);
                    mma16816(acc[sm][sn], a_hi[sm], b_lo[sn]);
                    mma16816(acc[sm][sn], a_lo[sm], b_hi[sn]);
                }
        }

        if (BMODE == 2 && it + 1 < n_iter) wload(it + 1, (it + 1) % 3);
        __syncthreads();
        if (it + 3 < n_iter) { copyTiles(it + 3, st); cp_commit(); }
    }

    // -------- epilogue --------
    #pragma unroll
    for (int sm = 0; sm < 2; sm++) {
        #pragma unroll
        for (int half = 0; half < 2; half++) {
            int r = i0 + warp_m * 32 + sm * 16 + (lane >> 2) + half * 8;
            #pragma unroll
            for (int sn = 0; sn < 8; sn++) {
                int c = j0 + warp_n * 64 + sn * 8 + (lane & 3) * 2;
                float v0 = acc[sm][sn][half * 2 + 0];
                float v1 = acc[sm][sn][half * 2 + 1];
                if (EPI >= 2) {
                    v0 += bias[(long long)bz * sBias + c];
                    v1 += bias[(long long)bz * sBias + c + 1];
                }
                if (EPI == 2) {
                    v0 = 0.5f * v0 * (1.0f + erff(v0 * 0.70710678118654752f));
                    v1 = 0.5f * v1 * (1.0f + erff(v1 * 0.70710678118654752f));
                }
                if (EPI == 0) {
                    float2 st2; st2.x = v0; st2.y = v1;
                    *(float2*)&Cf[(long long)bz * sC + (long long)r * Nq + c] = st2;
                } else {
                    long long idx;
                    if (EPI == 3) {
                        long long rr = (long long)(r >> 4) * SLOTS + (long long)bz * PP + (r & 15);
                        idx = rr * Nq + c;
                    } else {
                        idx = (long long)bz * sC + (long long)r * Nq + c;
                    }
                    uint32_t h, l;
                    split2(v0, v1, h, l);
                    *(uint32_t*)&Oh[idx] = h;
                    *(uint32_t*)&Ol[idx] = l;
                }
            }
        }
    }
}

// ==================== small kernels ====================
__device__ __forceinline__ float block_sum256(float v, float* sm) {
    int t = threadIdx.x;
    #pragma unroll
    for (int o = 16; o > 0; o >>= 1) v += __shfl_xor_sync(0xffffffffu, v, o);
    if ((t & 31) == 0) sm[t >> 5] = v;
    __syncthreads();
    if (t < 8) {
        float w = sm[t];
        #pragma unroll
        for (int o = 4; o > 0; o >>= 1) w += __shfl_xor_sync(0xffu, w, o);
        if (t == 0) sm[0] = w;
    }
    __syncthreads();
    v = sm[0];
    __syncthreads();
    return v;
}
__device__ __forceinline__ float block_max256(float v, float* sm) {
    int t = threadIdx.x;
    #pragma unroll
    for (int o = 16; o > 0; o >>= 1) v = fmaxf(v, __shfl_xor_sync(0xffffffffu, v, o));
    if ((t & 31) == 0) sm[t >> 5] = v;
    __syncthreads();
    if (t < 8) {
        float w = sm[t];
        #pragma unroll
        for (int o = 4; o > 0; o >>= 1) w = fmaxf(w, __shfl_xor_sync(0xffu, w, o));
        if (t == 0) sm[0] = w;
    }
    __syncthreads();
    v = sm[0];
    __syncthreads();
    return v;
}

// split x -> bf16 hi/lo
__global__ void split_kernel(const float* __restrict__ src,
                             __nv_bfloat16* __restrict__ h, __nv_bfloat16* __restrict__ l,
                             int n4) {
    int i = blockIdx.x * blockDim.x + threadIdx.x;
    if (i >= n4) return;
    float4 v = *(const float4*)&src[i * 4];
    uint32_t h0, l0, h1, l1;
    split2(v.x, v.y, h0, l0);
    split2(v.z, v.w, h1, l1);
    uint2 hv; hv.x = h0; hv.y = h1;
    uint2 lv; lv.x = l0; lv.y = l1;
    *(uint2*)&h[i * 4] = hv;
    *(uint2*)&l[i * 4] = lv;
}

// normalize phi over expert axis -> bf16 hi/lo [s][d]
__global__ void phi_norm_kernel(const float* __restrict__ phi) {
    int t = blockIdx.x * blockDim.x + threadIdx.x;
    if (t >= PP * DIM) return;
    float ss = 0.f;
    #pragma unroll 4
    for (int n = 0; n < NE; n++) {
        float v = phi[n * PP * DIM + t];
        ss += v * v;
    }
    float inv = rsqrtf(ss + 1e-6f);
    #pragma unroll 4
    for (int n = 0; n < NE; n++) {
        float v = phi[n * PP * DIM + t] * inv;
        __nv_bfloat16 h = __float2bfloat16_rn(v);
        g_ph[n * PP * DIM + t] = h;
        g_pl[n * PP * DIM + t] = __float2bfloat16_rn(v - __bfloat162float(h));
    }
}

// softmax over tokens m -> fp32 D [b][m][s]
__global__ void softmax_col_kernel(const float* __restrict__ L, float* __restrict__ Dout) {
    const int tx = threadIdx.x & 31, ty = threadIdx.x >> 5;
    const int s = blockIdx.x * 32 + tx;
    const float* Lb = L + (long long)blockIdx.y * MTOK * SLOTS;
    float* Db = Dout + (long long)blockIdx.y * MTOK * SLOTS;
    __shared__ float red[8][32];

    float mx = -1e30f;
    for (int m = ty; m < MTOK; m += 8)
        mx = fmaxf(mx, Lb[(long long)m * SLOTS + s]);
    red[ty][tx] = mx;
    __syncthreads();
    if (ty == 0) {
        float v = red[0][tx];
        #pragma unroll
        for (int q = 1; q < 8; q++) v = fmaxf(v, red[q][tx]);
        red[0][tx] = v;
    }
    __syncthreads();
    mx = red[0][tx];
    __syncthreads();

    float sum = 0.f;
    for (int m = ty; m < MTOK; m += 8) {
        float e = __expf(Lb[(long long)m * SLOTS + s] - mx);
        Db[(long long)m * SLOTS + s] = e;
        sum += e;
    }
    red[ty][tx] = sum;
    __syncthreads();
    if (ty == 0) {
        float v = 0.f;
        #pragma unroll
        for (int q = 0; q < 8; q++) v += red[q][tx];
        red[0][tx] = v;
    }
    __syncthreads();
    float inv = 1.0f / red[0][tx];
    for (int m = ty; m < MTOK; m += 8)
        Db[(long long)m * SLOTS + s] *= inv;
}

// transpose + split D [b][m][s] -> Dt hi/lo [b][s][m]
__global__ void dtrans_kernel(const float* __restrict__ D) {
    __shared__ float tile[32][33];
    const int s0 = blockIdx.x * 32, m0 = blockIdx.y * 32, b = blockIdx.z;
    const int tx = threadIdx.x & 31, ty = threadIdx.x >> 5;
    #pragma unroll
    for (int q = 0; q < 4; q++) {
        int m = m0 + ty + q * 8;
        tile[ty + q * 8][tx] = D[((long long)b * MTOK + m) * SLOTS + s0 + tx];
    }
    __syncthreads();
    #pragma unroll
    for (int q = 0; q < 4; q++) {
        int s = s0 + ty + q * 8;
        float v = tile[tx][ty + q * 8];
        long long o = ((long long)b * SLOTS + s) * MTOK + m0 + tx;
        __nv_bfloat16 h = __float2bfloat16_rn(v);
        g_Dth[o] = h;
        g_Dtl[o] = __float2bfloat16_rn(v - __bfloat162float(h));
    }
}

// softmax over slots s -> bf16 hi/lo C [b*m][s]
__global__ void softmax_row_kernel(const float* __restrict__ L) {
    const long long row = blockIdx.x;
    const float* Lr = L + row * SLOTS;
    __shared__ float sm[32];
    const int t = threadIdx.x;

    float v[4];
    float mx = -1e30f;
    #pragma unroll
    for (int q = 0; q < 4; q++) { v[q] = Lr[t + q * 256]; mx = fmaxf(mx, v[q]); }
    mx = block_max256(mx, sm);
    float sum = 0.f;
    #pragma unroll
    for (int q = 0; q < 4; q++) { v[q] = __expf(v[q] - mx); sum += v[q]; }
    sum = block_sum256(sum, sm);
    float inv = 1.0f / sum;
    #pragma unroll
    for (int q = 0; q < 4; q++) {
        float c = v[q] * inv;
        __nv_bfloat16 h = __float2bfloat16_rn(c);
        g_Ch[row * SLOTS + t + q * 256] = h;
        g_Cl[row * SLOTS + t + q * 256] = __float2bfloat16_rn(c - __bfloat162float(h));
    }
}

// LayerNorm rows of Xs -> bf16 hi/lo, expert-major [n][b*16+p][d]
__global__ void ln_kernel(const float* __restrict__ Xs,
                          const float* __restrict__ g, const float* __restrict__ bta) {
    const long long row = blockIdx.x;
    const int b = (int)(row / SLOTS);
    const int s = (int)(row % SLOTS);
    const int n = s >> 4, p = s & 15;
    const float* xr = Xs + row * DIM;
    long long obase = ((long long)n * (BATCH * PP) + b * PP + p) * DIM;
    __shared__ float sm[32];
    const int t = threadIdx.x;

    float v[3];
    float ss = 0.f;
    #pragma unroll
    for (int q = 0; q < 3; q++) { v[q] = xr[t + q * 256]; ss += v[q]; }
    float mu = block_sum256(ss, sm) * (1.0f / DIM);
    float sv = 0.f;
    #pragma unroll
    for (int q = 0; q < 3; q++) { float d = v[q] - mu; sv += d * d; }
    float var = block_sum256(sv, sm) * (1.0f / DIM);
    float inv = rsqrtf(var + 1e-5f);
    #pragma unroll
    for (int q = 0; q < 3; q++) {
        int c = t + q * 256;
        float o = (v[q] - mu) * inv * g[n * DIM + c] + bta[n * DIM + c];
        __nv_bfloat16 h = __float2bfloat16_rn(o);
        g_Xnh[obase + c] = h;
        g_Xnl[obase + c] = __float2bfloat16_rn(o - __bfloat162float(h));
    }
}

// ==================== launch ====================
extern "C" void kernel_launch(void* const* d_in, const int* in_sizes, int n_in,
                              void* d_out, int out_size) {
    const float* x    = (const float*)d_in[0];
    const float* phi  = (const float*)d_in[1];
    const float* ln_g = (const float*)d_in[2];
    const float* ln_b = (const float*)d_in[3];
    const float* w1   = (const float*)d_in[4];
    const float* b1   = (const float*)d_in[5];
    const float* w2   = (const float*)d_in[6];
    const float* b2   = (const float*)d_in[7];
    float* out = (float*)d_out;

    __nv_bfloat16 *xh, *xl, *ph, *pl, *Dth, *Dtl, *Ch, *Cl, *Xnh, *Xnl, *Hbh, *Hbl, *Ysh, *Ysl;
    float *logits, *Dm, *Xs;
    cudaGetSymbolAddress((void**)&xh, g_xh);   cudaGetSymbolAddress((void**)&xl, g_xl);
    cudaGetSymbolAddress((void**)&ph, g_ph);   cudaGetSymbolAddress((void**)&pl, g_pl);
    cudaGetSymbolAddress((void**)&logits, g_logits);
    cudaGetSymbolAddress((void**)&Dm, g_D);
    cudaGetSymbolAddress((void**)&Dth, g_Dth); cudaGetSymbolAddress((void**)&Dtl, g_Dtl);
    cudaGetSymbolAddress((void**)&Ch, g_Ch);   cudaGetSymbolAddress((void**)&Cl, g_Cl);
    cudaGetSymbolAddress((void**)&Xs, g_Xs);
    cudaGetSymbolAddress((void**)&Xnh, g_Xnh); cudaGetSymbolAddress((void**)&Xnl, g_Xnl);
    cudaGetSymbolAddress((void**)&Hbh, g_Hbh); cudaGetSymbolAddress((void**)&Hbl, g_Hbl);
    cudaGetSymbolAddress((void**)&Ysh, g_Ysh); cudaGetSymbolAddress((void**)&Ysl, g_Ysl);

    cudaFuncSetAttribute(tc_gemm<0, 0>, cudaFuncAttributeMaxDynamicSharedMemorySize, SMEM_SZ);
    cudaFuncSetAttribute(tc_gemm<1, 0>, cudaFuncAttributeMaxDynamicSharedMemorySize, SMEM_SZ);
    cudaFuncSetAttribute(tc_gemm<2, 2>, cudaFuncAttributeMaxDynamicSharedMemorySize, SMEM_SZ);
    cudaFuncSetAttribute(tc_gemm<2, 3>, cudaFuncAttributeMaxDynamicSharedMemorySize, SMEM_SZ);

    // 1) split x; normalize+split phi
    split_kernel<<<(BATCH * MTOK * DIM / 4 + 255) / 256, 256>>>(x, xh, xl, BATCH * MTOK * DIM / 4);
    phi_norm_kernel<<<(PP * DIM + 255) / 256, 256>>>(phi);

    // 2) logits[b] = X[b] * phin^T   (A=x K-contig, B=phin K-contig)
    tc_gemm<0, 0><<<dim3(MTOK / 128, SLOTS / 128, BATCH), 256, SMEM_SZ>>>(
        xh, xl, ph, pl, logits, nullptr, nullptr, nullptr,
        MTOK, SLOTS, DIM,
        (long long)MTOK * DIM, 0LL, (long long)MTOK * SLOTS, 0LL);

    // 3) softmaxes: D (fp32, then transposed+split), C (bf16 pair)
    softmax_col_kernel<<<dim3(SLOTS / 32, BATCH), 256>>>(logits, Dm);
    dtrans_kernel<<<dim3(SLOTS / 32, MTOK / 32, BATCH), 256>>>(Dm);
    softmax_row_kernel<<<BATCH * MTOK, 256>>>(logits);

    // 4) Xs[b][s][d] = sum_m Dt[s][m] * x[m][d]   (A=Dt K-contig, B=x KxN trans)
    tc_gemm<1, 0><<<dim3(SLOTS / 128, DIM / 128, BATCH), 256, SMEM_SZ>>>(
        Dth, Dtl, xh, xl, Xs, nullptr, nullptr, nullptr,
        SLOTS, DIM, MTOK,
        (long long)SLOTS * MTOK, (long long)MTOK * DIM, (long long)SLOTS * DIM, 0LL);

    // 5) LayerNorm -> expert-major bf16 pair
    ln_kernel<<<BATCH * SLOTS, 256>>>(Xs, ln_g, ln_b);

    // 6) per-expert H = GELU(Xn*W1 + b1) -> bf16 pair
    tc_gemm<2, 2><<<dim3(1, HID / 128, NE), 256, SMEM_SZ>>>(
        Xnh, Xnl, w1, nullptr, nullptr, Hbh, Hbl, b1,
        BATCH * PP, HID, DIM,
        (long long)BATCH * PP * DIM, (long long)DIM * HID,
        (long long)BATCH * PP * HID, (long long)HID);

    // 7) per-expert Ys = H*W2 + b2, scattered to [b][s][d] bf16 pair
    tc_gemm<2, 3><<<dim3(1, DIM / 128, NE), 256, SMEM_SZ>>>(
        Hbh, Hbl, w2, nullptr, nullptr, Ysh, Ysl, b2,
        BATCH * PP, DIM, HID,
        (long long)BATCH * PP * HID, (long long)HID * DIM,
        0LL, (long long)DIM);

    // 8) Y[b] = C[b] * Ys[b]   (A=C K-contig, B=Ys KxN trans)
    tc_gemm<1, 0><<<dim3(MTOK / 128, DIM / 128, BATCH), 256, SMEM_SZ>>>(
        Ch, Cl, Ysh, Ysl, out, nullptr, nullptr, nullptr,
        MTOK, DIM, SLOTS,
        (long long)MTOK * SLOTS, (long long)SLOTS * DIM, (long long)MTOK * DIM, 0LL);
}